// round 1
// baseline (speedup 1.0000x reference)
#include <cuda_runtime.h>

#define GRID7 7
#define GG    49          // 7*7
#define CQ    64
#define NEGV  (-1e20f)

// Softmax probabilities scratch: [n][49][16] (14 used, padded to 16 for float4)
__device__ float g_p[512 * GG * 16];

// ---------------------------------------------------------------------------
// Kernel A: per-n logits (H masked-diag + W) and softmax over 14.
// grid = N, block = 256. Static smem ~28.6 KB -> ~7 blocks/SM, single wave.
// ---------------------------------------------------------------------------
__global__ __launch_bounds__(256) void ax_attn_logits(
    const float* __restrict__ qH, const float* __restrict__ kH,
    const float* __restrict__ qW, const float* __restrict__ kW)
{
    __shared__ float sQ[GG * 65];          // [g][c], g = major*7+minor, pad 65 (banks distinct per g)
    __shared__ float sK[6 * 456 + 448];    // [g][c*7+j], g-stride 456 (mod 32 = 8 -> disjoint banks)
    __shared__ float sL[GG * 16];          // logits [h*7+w][14]

    const int n   = blockIdx.x;
    const int tid = threadIdx.x;

    // ---- pass 1: H ----
    {
        const float* qs = qH + (size_t)n * (GG * CQ);
        const float* ks = kH + (size_t)n * (GG * CQ);
        for (int i = tid; i < GG * CQ; i += 256)
            sQ[(i >> 6) * 65 + (i & 63)] = qs[i];
        for (int i = tid; i < GG * CQ; i += 256) {
            int w = i / 448, r = i % 448;
            sK[w * 456 + r] = ks[i];
        }
    }
    __syncthreads();

    // eH[w,h,j] = sum_c qH[n,w,h,c]*kH[n,w,c,j]; store at sL[(h*7+w)*16 + j]
    for (int idx = tid; idx < 343; idx += 256) {
        int w = idx / 49, r = idx % 49, h = r / 7, j = r % 7;
        const float* q = &sQ[(w * 7 + h) * 65];
        const float* k = &sK[w * 456 + j];
        float s = 0.f;
        #pragma unroll
        for (int c = 0; c < CQ; c++) s = fmaf(q[c], k[c * 7], s);
        sL[(h * 7 + w) * 16 + j] = (h == j) ? NEGV : s;
    }
    __syncthreads();

    // ---- pass 2: W (reuse sQ/sK) ----
    {
        const float* qs = qW + (size_t)n * (GG * CQ);
        const float* ks = kW + (size_t)n * (GG * CQ);
        for (int i = tid; i < GG * CQ; i += 256)
            sQ[(i >> 6) * 65 + (i & 63)] = qs[i];
        for (int i = tid; i < GG * CQ; i += 256) {
            int h = i / 448, r = i % 448;
            sK[h * 456 + r] = ks[i];
        }
    }
    __syncthreads();

    // eW[h,w,y] = sum_c qW[n,h,w,c]*kW[n,h,c,y]; store at sL[(h*7+w)*16 + 7 + y]
    for (int idx = tid; idx < 343; idx += 256) {
        int h = idx / 49, r = idx % 49, w = r / 7, y = r % 7;
        const float* q = &sQ[(h * 7 + w) * 65];
        const float* k = &sK[h * 456 + y];
        float s = 0.f;
        #pragma unroll
        for (int c = 0; c < CQ; c++) s = fmaf(q[c], k[c * 7], s);
        sL[(h * 7 + w) * 16 + 7 + y] = s;
    }
    __syncthreads();

    // softmax over 14 per position, write to scratch (padded 16)
    if (tid < GG) {
        const float* row = &sL[tid * 16];
        float m = row[0];
        #pragma unroll
        for (int i = 1; i < 14; i++) m = fmaxf(m, row[i]);
        float e[14], sum = 0.f;
        #pragma unroll
        for (int i = 0; i < 14; i++) { e[i] = __expf(row[i] - m); sum += e[i]; }
        float inv = 1.f / sum;
        float* dst = &g_p[((size_t)n * GG + tid) * 16];
        #pragma unroll
        for (int i = 0; i < 14; i++) dst[i] = e[i] * inv;
        dst[14] = 0.f; dst[15] = 0.f;
    }
}

// ---------------------------------------------------------------------------
// Kernel B: out[n,c,h,w] = sum_j p[n,h,w,j]*vH[n,w,c,j] + sum_y p[n,h,w,7+y]*vW[n,h,c,y]
// grid = (N, Cv/256), block = 256 (lane = c within chunk).
// Dynamic smem 103.5 KB -> 2 blocks/SM (16 warps). vH cached in 49 regs/thread,
// p read as float4 broadcasts, output staged in smem (aliases consumed vH) for
// coalesced float4 stores.
// ---------------------------------------------------------------------------
__global__ __launch_bounds__(256, 2) void ax_attn_out(
    const float* __restrict__ vH, const float* __restrict__ vW,
    float* __restrict__ out, int Cv)
{
    extern __shared__ float sm[];
    float* sVH = sm;             // 7*256*7 = 12544 floats (reused as sOut)
    float* sVW = sm + 12544;     // 12544 floats
    float* sP  = sm + 25088;     // 49*16 = 784 floats

    const int n   = blockIdx.x;
    const int c0  = blockIdx.y * 256;
    const int tid = threadIdx.x;

    // stage p (float4, coalesced)
    {
        const float4* src = (const float4*)&g_p[(size_t)n * GG * 16];
        for (int i = tid; i < 196; i += 256) ((float4*)sP)[i] = src[i];
    }
    // stage vH chunk: per w a contiguous 1792-float run (float4 aligned: 256*7 % 4 == 0)
    for (int i = tid; i < 3136; i += 256) {
        int w = i / 448, r = i % 448;
        const float4* src = (const float4*)(vH + ((size_t)(n * 7 + w) * Cv + c0) * 7);
        ((float4*)(sVH + w * 1792))[r] = src[r];
    }
    // stage vW chunk
    for (int i = tid; i < 3136; i += 256) {
        int h = i / 448, r = i % 448;
        const float4* src = (const float4*)(vW + ((size_t)(n * 7 + h) * Cv + c0) * 7);
        ((float4*)(sVW + h * 1792))[r] = src[r];
    }
    __syncthreads();

    // cache this thread's vH rows (lane stride 7 floats -> conflict-free)
    float vh[49];
    #pragma unroll
    for (int w = 0; w < 7; w++)
        #pragma unroll
        for (int j = 0; j < 7; j++)
            vh[w * 7 + j] = sVH[w * 1792 + tid * 7 + j];
    __syncthreads();   // all vH consumed before aliasing as sOut

    float* sOut = sVH;
    #pragma unroll
    for (int h = 0; h < 7; h++) {
        float vw[7];
        #pragma unroll
        for (int y = 0; y < 7; y++) vw[y] = sVW[h * 1792 + tid * 7 + y];

        #pragma unroll
        for (int w = 0; w < 7; w++) {
            const float4* p4 = (const float4*)&sP[(h * 7 + w) * 16];
            float4 a = p4[0], b = p4[1], c = p4[2], d = p4[3];
            float acc;
            acc  = a.x * vh[w * 7 + 0];
            acc = fmaf(a.y, vh[w * 7 + 1], acc);
            acc = fmaf(a.z, vh[w * 7 + 2], acc);
            acc = fmaf(a.w, vh[w * 7 + 3], acc);
            acc = fmaf(b.x, vh[w * 7 + 4], acc);
            acc = fmaf(b.y, vh[w * 7 + 5], acc);
            acc = fmaf(b.z, vh[w * 7 + 6], acc);
            acc = fmaf(b.w, vw[0], acc);
            acc = fmaf(c.x, vw[1], acc);
            acc = fmaf(c.y, vw[2], acc);
            acc = fmaf(c.z, vw[3], acc);
            acc = fmaf(c.w, vw[4], acc);
            acc = fmaf(d.x, vw[5], acc);
            acc = fmaf(d.y, vw[6], acc);
            // lane stride 49 -> 49 mod 32 = 17 (coprime) -> conflict-free
            sOut[tid * 49 + h * 7 + w] = acc;
        }
    }
    __syncthreads();

    // coalesced float4 write: sOut[c_local*49 + pos] == out[n, c0+c_local, pos]
    float* dst = out + (size_t)n * Cv * GG + (size_t)c0 * GG;
    for (int i = tid; i < 3136; i += 256)
        ((float4*)dst)[i] = ((const float4*)sOut)[i];
}

// ---------------------------------------------------------------------------
extern "C" void kernel_launch(void* const* d_in, const int* in_sizes, int n_in,
                              void* d_out, int out_size)
{
    const float* qH = (const float*)d_in[0];
    const float* kH = (const float*)d_in[1];
    const float* vH = (const float*)d_in[2];
    const float* qW = (const float*)d_in[3];
    const float* kW = (const float*)d_in[4];
    const float* vW = (const float*)d_in[5];

    const int B  = in_sizes[0] / (GRID7 * CQ);   // 3584
    const int N  = B / GRID7;                    // 512
    const int Cv = in_sizes[2] / (B * GRID7);    // 512

    const size_t smemB = (size_t)(12544 + 12544 + 784) * sizeof(float); // 103488
    cudaFuncSetAttribute(ax_attn_out, cudaFuncAttributeMaxDynamicSharedMemorySize, (int)smemB);

    ax_attn_logits<<<N, 256>>>(qH, kH, qW, kW);
    ax_attn_out<<<dim3(N, Cv / 256), 256, smemB>>>(vH, vW, (float*)d_out, Cv);
}

// round 3
// speedup vs baseline: 1.0766x; 1.0766x over previous
#include <cuda_runtime.h>

#define GG    49
#define CQ    64
#define NEGV  (-1e20f)

// Softmax probabilities scratch: [n][49][16]; pH at slots 0..6, pW at slots 8..14.
__device__ float g_p[512 * GG * 16];

// ---------------------------------------------------------------------------
// Kernel A: logits (H diag-masked + W) + softmax over 14, per n.
// grid = N, block = 384. Dyn smem 56448 B -> 4 blocks/SM (48 warps, 75% occ).
// K tensors staged TRANSPOSED so each dot is 32 x LDS.128.
// ---------------------------------------------------------------------------
__global__ __launch_bounds__(384) void ax_attn_logits(
    const float* __restrict__ qH, const float* __restrict__ kH,
    const float* __restrict__ qW, const float* __restrict__ kW)
{
    extern __shared__ float smA[];
    float* sQH = smA;              // 49 rows * 68 (float4-aligned row stride)
    float* sKH = smA + 3332;       // transposed: row (w*7+j), cols c
    float* sQW = smA + 6664;
    float* sKW = smA + 9996;
    float* sL  = smA + 13328;      // 49*16 logits

    const int n   = blockIdx.x;
    const int tid = threadIdx.x;

    // ---- stage q (direct, float4) and k (transposed scatter) ----
    {
        const float4* q1 = (const float4*)(qH + (size_t)n * 3136);
        const float4* q2 = (const float4*)(qW + (size_t)n * 3136);
        for (int i4 = tid; i4 < 784; i4 += 384) {
            int g = i4 >> 4, c4 = i4 & 15;
            ((float4*)(sQH + g * 68))[c4] = q1[i4];
            ((float4*)(sQW + g * 68))[c4] = q2[i4];
        }
        const float4* k1 = (const float4*)(kH + (size_t)n * 3136);
        const float4* k2 = (const float4*)(kW + (size_t)n * 3136);
        for (int i4 = tid; i4 < 784; i4 += 384) {
            float4 a = k1[i4], b = k2[i4];
            float av[4] = {a.x, a.y, a.z, a.w};
            float bv[4] = {b.x, b.y, b.z, b.w};
            int base = i4 * 4;
            #pragma unroll
            for (int e = 0; e < 4; e++) {
                int i = base + e;
                int w = i / 448, r = i - w * 448, c = r / 7, j = r - c * 7;
                sKH[(w * 7 + j) * 68 + c] = av[e];
                sKW[(w * 7 + j) * 68 + c] = bv[e];
            }
        }
    }
    __syncthreads();

    if (tid < 343) {
        // H: tid = w*49 + h*7 + j  ->  logits[n,h,w,j] = dot(qH[n,w,h,:], kH[n,w,:,j])
        int a0 = tid / 49, r = tid - a0 * 49, a1 = r / 7, a2 = r - a1 * 7;
        {
            const float4* q = (const float4*)(sQH + (a0 * 7 + a1) * 68);
            const float4* k = (const float4*)(sKH + (a0 * 7 + a2) * 68);
            float s = 0.f;
            #pragma unroll
            for (int c4 = 0; c4 < 16; c4++) {
                float4 qa = q[c4], ka = k[c4];
                s = fmaf(qa.x, ka.x, s); s = fmaf(qa.y, ka.y, s);
                s = fmaf(qa.z, ka.z, s); s = fmaf(qa.w, ka.w, s);
            }
            sL[(a1 * 7 + a0) * 16 + a2] = (a1 == a2) ? NEGV : s;
        }
        // W: tid = h*49 + w*7 + y  ->  logits[n,h,w,7+y] = dot(qW[n,h,w,:], kW[n,h,:,y])
        {
            const float4* q = (const float4*)(sQW + (a0 * 7 + a1) * 68);
            const float4* k = (const float4*)(sKW + (a0 * 7 + a2) * 68);
            float s = 0.f;
            #pragma unroll
            for (int c4 = 0; c4 < 16; c4++) {
                float4 qa = q[c4], ka = k[c4];
                s = fmaf(qa.x, ka.x, s); s = fmaf(qa.y, ka.y, s);
                s = fmaf(qa.z, ka.z, s); s = fmaf(qa.w, ka.w, s);
            }
            sL[(a0 * 7 + a1) * 16 + 8 + a2] = s;
        }
    }
    __syncthreads();

    // softmax over slots {0..6, 8..14}
    if (tid < GG) {
        const float* row = sL + tid * 16;
        float m = row[0];
        #pragma unroll
        for (int i = 1; i < 7; i++) m = fmaxf(m, row[i]);
        #pragma unroll
        for (int i = 8; i < 15; i++) m = fmaxf(m, row[i]);
        float e[16], sum = 0.f;
        #pragma unroll
        for (int i = 0; i < 7; i++)  { e[i] = __expf(row[i] - m); sum += e[i]; }
        #pragma unroll
        for (int i = 8; i < 15; i++) { e[i] = __expf(row[i] - m); sum += e[i]; }
        e[7] = 0.f; e[15] = 0.f;
        float inv = 1.f / sum;
        float* dst = &g_p[((size_t)n * GG + tid) * 16];
        #pragma unroll
        for (int i = 0; i < 16; i++) dst[i] = e[i] * inv;
    }
}

// ---------------------------------------------------------------------------
// Kernel B: out[n,c,h,w] = sum_j p[pos][j]*vH[n,w,c,j] + sum_y p[pos][8+y]*vW[n,h,c,y]
// grid = (N, Cv/128), block = 128 (lane = c within 128-chunk).
// One 25KB V-buffer reused sequentially (vH, then vW, then aliased as sOut).
// V stored transposed [g][j][c] -> conflict-free lane-contiguous LDS.
// smem 28.2KB, 6 blocks/SM = 24 warps.
// ---------------------------------------------------------------------------
__global__ __launch_bounds__(128, 6) void ax_attn_out(
    const float* __restrict__ vH, const float* __restrict__ vW,
    float* __restrict__ out, int Cv)
{
    __shared__ float sV[7 * 7 * 128];   // [g][j][c] = 6272 floats (reused as sOut)
    __shared__ float sP[GG * 16];       // 784

    const int n   = blockIdx.x;
    const int c0  = blockIdx.y * 128;
    const int tid = threadIdx.x;

    // stage p
    {
        const float4* src = (const float4*)&g_p[(size_t)n * GG * 16];
        for (int i = tid; i < 196; i += 128) ((float4*)sP)[i] = src[i];
    }
    // stage vH chunk, transposed: sV[w*896 + j*128 + c]
    for (int i4 = tid; i4 < 1568; i4 += 128) {
        int w = i4 / 224, r4 = i4 - w * 224;
        float4 v = ((const float4*)(vH + ((size_t)(n * 7 + w) * Cv + c0) * 7))[r4];
        float vv[4] = {v.x, v.y, v.z, v.w};
        int base = r4 * 4;
        #pragma unroll
        for (int e = 0; e < 4; e++) {
            int i = base + e, c = i / 7, j = i - c * 7;
            sV[w * 896 + j * 128 + c] = vv[e];
        }
    }
    __syncthreads();

    float acc[49];
    // H part
    #pragma unroll
    for (int w = 0; w < 7; w++) {
        float v0 = sV[w * 896 + 0 * 128 + tid];
        float v1 = sV[w * 896 + 1 * 128 + tid];
        float v2 = sV[w * 896 + 2 * 128 + tid];
        float v3 = sV[w * 896 + 3 * 128 + tid];
        float v4 = sV[w * 896 + 4 * 128 + tid];
        float v5 = sV[w * 896 + 5 * 128 + tid];
        float v6 = sV[w * 896 + 6 * 128 + tid];
        #pragma unroll
        for (int h = 0; h < 7; h++) {
            const float4* p4 = (const float4*)(sP + (h * 7 + w) * 16);
            float4 a = p4[0], b = p4[1];
            float s = a.x * v0;
            s = fmaf(a.y, v1, s); s = fmaf(a.z, v2, s); s = fmaf(a.w, v3, s);
            s = fmaf(b.x, v4, s); s = fmaf(b.y, v5, s); s = fmaf(b.z, v6, s);
            acc[h * 7 + w] = s;
        }
    }
    __syncthreads();   // all vH reads done

    // stage vW chunk (same buffer), transposed: sV[h*896 + y*128 + c]
    for (int i4 = tid; i4 < 1568; i4 += 128) {
        int h = i4 / 224, r4 = i4 - h * 224;
        float4 v = ((const float4*)(vW + ((size_t)(n * 7 + h) * Cv + c0) * 7))[r4];
        float vv[4] = {v.x, v.y, v.z, v.w};
        int base = r4 * 4;
        #pragma unroll
        for (int e = 0; e < 4; e++) {
            int i = base + e, c = i / 7, y = i - c * 7;
            sV[h * 896 + y * 128 + c] = vv[e];
        }
    }
    __syncthreads();

    // W part
    #pragma unroll
    for (int h = 0; h < 7; h++) {
        float v0 = sV[h * 896 + 0 * 128 + tid];
        float v1 = sV[h * 896 + 1 * 128 + tid];
        float v2 = sV[h * 896 + 2 * 128 + tid];
        float v3 = sV[h * 896 + 3 * 128 + tid];
        float v4 = sV[h * 896 + 4 * 128 + tid];
        float v5 = sV[h * 896 + 5 * 128 + tid];
        float v6 = sV[h * 896 + 6 * 128 + tid];
        #pragma unroll
        for (int w = 0; w < 7; w++) {
            const float4* p4 = (const float4*)(sP + (h * 7 + w) * 16);
            float4 c4 = p4[2], d4 = p4[3];
            float s = acc[h * 7 + w];
            s = fmaf(c4.x, v0, s); s = fmaf(c4.y, v1, s); s = fmaf(c4.z, v2, s);
            s = fmaf(c4.w, v3, s); s = fmaf(d4.x, v4, s); s = fmaf(d4.y, v5, s);
            s = fmaf(d4.z, v6, s);
            acc[h * 7 + w] = s;
        }
    }
    __syncthreads();   // all vW reads done; safe to alias

    // stage output (lane stride 49 -> 17 mod 32 -> conflict-free)
    float* sOut = sV;
    #pragma unroll
    for (int pos = 0; pos < 49; pos++) sOut[tid * 49 + pos] = acc[pos];
    __syncthreads();

    // coalesced float4 write: sOut[c_local*49 + pos] == out[n, c0+c_local, pos]
    float* dst = out + ((size_t)n * Cv + c0) * GG;
    for (int i = tid; i < 1568; i += 128)
        ((float4*)dst)[i] = ((const float4*)sOut)[i];
}

// ---------------------------------------------------------------------------
extern "C" void kernel_launch(void* const* d_in, const int* in_sizes, int n_in,
                              void* d_out, int out_size)
{
    const float* qH = (const float*)d_in[0];
    const float* kH = (const float*)d_in[1];
    const float* vH = (const float*)d_in[2];
    const float* qW = (const float*)d_in[3];
    const float* kW = (const float*)d_in[4];
    const float* vW = (const float*)d_in[5];

    const int B  = in_sizes[0] / (7 * CQ);    // 3584
    const int N  = B / 7;                     // 512
    const int Cv = in_sizes[2] / (B * 7);     // 512

    const size_t smemA = (size_t)(4 * 3332 + 784) * sizeof(float);  // 56448
    cudaFuncSetAttribute(ax_attn_logits, cudaFuncAttributeMaxDynamicSharedMemorySize, (int)smemA);

    ax_attn_logits<<<N, 384, smemA>>>(qH, kH, qW, kW);
    ax_attn_out<<<dim3(N, Cv / 128), 128>>>(vH, vW, (float*)d_out, Cv);
}

// round 4
// speedup vs baseline: 1.4780x; 1.3729x over previous
#include <cuda_runtime.h>

#define GG    49
#define CQ    64
#define NEGV  (-1e20f)

// Softmax probabilities scratch: [n][49][16]; pH at slots 0..6 (7=0), pW at 8..14 (15=0).
__device__ float g_p[512 * GG * 16];

// ---------------------------------------------------------------------------
// Kernel A: logits (H diag-masked + W) + softmax over 14, per n.
// grid = N, block = 384, dyn smem 55104 B -> 4 blocks/SM.
// Pure float4 staging (no transpose, no div-scatter). Dots: q as float4 from
// 68-padded rows; k natural layout, stride-7 scalar reads (broadcast groups).
// ---------------------------------------------------------------------------
__global__ __launch_bounds__(384) void ax_attn_logits(
    const float* __restrict__ qH, const float* __restrict__ kH,
    const float* __restrict__ qW, const float* __restrict__ kW)
{
    extern __shared__ float smA[];
    float* sQH = smA;            // 49 * 68
    float* sKH = smA + 3332;     // 7 * 452 (448 data + pad)
    float* sQW = smA + 6496;     // 49 * 68
    float* sKW = smA + 9828;     // 7 * 452
    float* sL  = smA + 12992;    // 49 * 16

    const int n   = blockIdx.x;
    const int tid = threadIdx.x;

    {
        const float4* q1 = (const float4*)(qH + (size_t)n * 3136);
        const float4* q2 = (const float4*)(qW + (size_t)n * 3136);
        const float4* k1 = (const float4*)(kH + (size_t)n * 3136);
        const float4* k2 = (const float4*)(kW + (size_t)n * 3136);
        for (int i4 = tid; i4 < 784; i4 += 384) {
            int g  = i4 >> 4,  c4 = i4 & 15;       // q: row g (64 floats), pad 68
            int w  = i4 / 112, r4 = i4 - w * 112;  // k: row w (448 floats), pad 452
            ((float4*)(sQH + g * 68))[c4]  = q1[i4];
            ((float4*)(sQW + g * 68))[c4]  = q2[i4];
            ((float4*)(sKH + w * 452))[r4] = k1[i4];
            ((float4*)(sKW + w * 452))[r4] = k2[i4];
        }
    }
    __syncthreads();

    if (tid < 343) {
        const int a0 = tid / 49;
        const int r  = tid - a0 * 49;
        const int a1 = r / 7;
        const int a2 = r - a1 * 7;

        // H: logits[n,h=a1,w=a0,a2] = dot(qH[n,a0,a1,:], kH[n,a0,:,a2])
        {
            const float4* q = (const float4*)(sQH + (a0 * 7 + a1) * 68);
            const float*  k = sKH + a0 * 452 + a2;
            float s = 0.f;
            #pragma unroll
            for (int c4 = 0; c4 < 16; c4++) {
                float4 qa = q[c4];
                s = fmaf(qa.x, k[(4 * c4 + 0) * 7], s);
                s = fmaf(qa.y, k[(4 * c4 + 1) * 7], s);
                s = fmaf(qa.z, k[(4 * c4 + 2) * 7], s);
                s = fmaf(qa.w, k[(4 * c4 + 3) * 7], s);
            }
            sL[(a1 * 7 + a0) * 16 + a2] = (a1 == a2) ? NEGV : s;
        }
        // W: logits[n,h=a0,w=a1,8+a2] = dot(qW[n,a0,a1,:], kW[n,a0,:,a2])
        {
            const float4* q = (const float4*)(sQW + (a0 * 7 + a1) * 68);
            const float*  k = sKW + a0 * 452 + a2;
            float s = 0.f;
            #pragma unroll
            for (int c4 = 0; c4 < 16; c4++) {
                float4 qa = q[c4];
                s = fmaf(qa.x, k[(4 * c4 + 0) * 7], s);
                s = fmaf(qa.y, k[(4 * c4 + 1) * 7], s);
                s = fmaf(qa.z, k[(4 * c4 + 2) * 7], s);
                s = fmaf(qa.w, k[(4 * c4 + 3) * 7], s);
            }
            sL[(a0 * 7 + a1) * 16 + 8 + a2] = s;
        }
    }
    __syncthreads();

    if (tid < GG) {
        const float* row = sL + tid * 16;
        float m = row[0];
        #pragma unroll
        for (int i = 1; i < 7; i++)  m = fmaxf(m, row[i]);
        #pragma unroll
        for (int i = 8; i < 15; i++) m = fmaxf(m, row[i]);
        float e[16], sum = 0.f;
        #pragma unroll
        for (int i = 0; i < 7; i++)  { e[i] = __expf(row[i] - m); sum += e[i]; }
        #pragma unroll
        for (int i = 8; i < 15; i++) { e[i] = __expf(row[i] - m); sum += e[i]; }
        e[7] = 0.f; e[15] = 0.f;
        float inv = 1.f / sum;
        float* dst = &g_p[((size_t)n * GG + tid) * 16];
        #pragma unroll
        for (int i = 0; i < 16; i++) dst[i] = e[i] * inv;
    }
}

// ---------------------------------------------------------------------------
// Kernel B: out[n,c,h,w] = sum_j p[pos][j]*vH[n,w,c,j] + sum_y p[pos][8+y]*vW[n,h,c,y]
// grid = (N, Cv/128), block = 128 (lane = channel in 128-chunk).
// V staged in NATURAL layout via pure float4 copy (vH+vW upfront, one sync).
// Compute reads lane-stride-7 (coprime 32 -> conflict-free). vh cached in 49
// regs; single fused pass computes the full 14-term sum per output and stores
// to sOut (aliasing consumed sVH). Dyn smem 53312 B -> 4 blocks/SM, ~90 regs.
// ---------------------------------------------------------------------------
__global__ __launch_bounds__(128, 4) void ax_attn_out(
    const float* __restrict__ vH, const float* __restrict__ vW,
    float* __restrict__ out, int Cv)
{
    extern __shared__ float smB[];
    float* sVH = smB;            // [w][c][j] = 7*128*7 = 6272 (later aliased as sOut)
    float* sVW = smB + 6272;     // [h][c][j]
    float* sP  = smB + 12544;    // 49*16

    const int n   = blockIdx.x;
    const int c0  = blockIdx.y * 128;
    const int tid = threadIdx.x;

    // stage vH + vW (pure float4, per-g rows contiguous) and p
    for (int i4 = tid; i4 < 1568; i4 += 128) {
        int g = i4 / 224, r4 = i4 - g * 224;
        ((float4*)(sVH + g * 896))[r4] =
            ((const float4*)(vH + ((size_t)(n * 7 + g) * Cv + c0) * 7))[r4];
        ((float4*)(sVW + g * 896))[r4] =
            ((const float4*)(vW + ((size_t)(n * 7 + g) * Cv + c0) * 7))[r4];
    }
    {
        const float4* src = (const float4*)&g_p[(size_t)n * GG * 16];
        for (int i = tid; i < 196; i += 128) ((float4*)sP)[i] = src[i];
    }
    __syncthreads();

    // cache this thread's vH (lane stride 7 -> conflict-free)
    float vh[49];
    #pragma unroll
    for (int w = 0; w < 7; w++)
        #pragma unroll
        for (int j = 0; j < 7; j++)
            vh[w * 7 + j] = sVH[w * 896 + tid * 7 + j];
    __syncthreads();   // all vH consumed -> safe to alias as sOut

    float* sOut = sVH;
    #pragma unroll
    for (int h = 0; h < 7; h++) {
        float vw0 = sVW[h * 896 + tid * 7 + 0];
        float vw1 = sVW[h * 896 + tid * 7 + 1];
        float vw2 = sVW[h * 896 + tid * 7 + 2];
        float vw3 = sVW[h * 896 + tid * 7 + 3];
        float vw4 = sVW[h * 896 + tid * 7 + 4];
        float vw5 = sVW[h * 896 + tid * 7 + 5];
        float vw6 = sVW[h * 896 + tid * 7 + 6];
        #pragma unroll
        for (int w = 0; w < 7; w++) {
            const float4* p4 = (const float4*)(sP + (h * 7 + w) * 16);
            float4 a = p4[0], b = p4[1], c4 = p4[2], d4 = p4[3];
            float s = a.x * vh[w * 7 + 0];
            s = fmaf(a.y, vh[w * 7 + 1], s);
            s = fmaf(a.z, vh[w * 7 + 2], s);
            s = fmaf(a.w, vh[w * 7 + 3], s);
            s = fmaf(b.x, vh[w * 7 + 4], s);
            s = fmaf(b.y, vh[w * 7 + 5], s);
            s = fmaf(b.z, vh[w * 7 + 6], s);
            s = fmaf(c4.x, vw0, s);
            s = fmaf(c4.y, vw1, s);
            s = fmaf(c4.z, vw2, s);
            s = fmaf(c4.w, vw3, s);
            s = fmaf(d4.x, vw4, s);
            s = fmaf(d4.y, vw5, s);
            s = fmaf(d4.z, vw6, s);
            // lane stride 49 (coprime 32) -> conflict-free
            sOut[tid * 49 + h * 7 + w] = s;
        }
    }
    __syncthreads();

    // coalesced float4 write: sOut[c_local*49 + pos] == out[n, c0+c_local, pos]
    float* dst = out + ((size_t)n * Cv + c0) * GG;
    for (int i = tid; i < 1568; i += 128)
        ((float4*)dst)[i] = ((const float4*)sOut)[i];
}

// ---------------------------------------------------------------------------
extern "C" void kernel_launch(void* const* d_in, const int* in_sizes, int n_in,
                              void* d_out, int out_size)
{
    const float* qH = (const float*)d_in[0];
    const float* kH = (const float*)d_in[1];
    const float* vH = (const float*)d_in[2];
    const float* qW = (const float*)d_in[3];
    const float* kW = (const float*)d_in[4];
    const float* vW = (const float*)d_in[5];

    const int B  = in_sizes[0] / (7 * CQ);    // 3584
    const int N  = B / 7;                     // 512
    const int Cv = in_sizes[2] / (B * 7);     // 512

    const size_t smemA = (size_t)(13776) * sizeof(float);  // 55104
    const size_t smemB = (size_t)(13328) * sizeof(float);  // 53312
    cudaFuncSetAttribute(ax_attn_logits, cudaFuncAttributeMaxDynamicSharedMemorySize, (int)smemA);
    cudaFuncSetAttribute(ax_attn_out,    cudaFuncAttributeMaxDynamicSharedMemorySize, (int)smemB);

    ax_attn_logits<<<N, 384, smemA>>>(qH, kH, qW, kW);
    ax_attn_out<<<dim3(N, Cv / 128), 128, smemB>>>(vH, vW, (float*)d_out, Cv);
}

// round 5
// speedup vs baseline: 1.8745x; 1.2682x over previous
#include <cuda_runtime.h>

#define GG    49
#define CQ    64
#define NEGV  (-1e20f)

// Softmax probabilities scratch: [n][49][16]; pH at slots 0..6 (7=0), pW at 8..14 (15=0).
__device__ float g_p[512 * GG * 16];

// ---------------------------------------------------------------------------
// Kernel A: logits (H diag-masked + W) + softmax over 14, per n.
// grid = N, block = 384, dyn smem 56448 B -> 4 blocks/SM (48 warps).
// Staging: burst-batched LDG.128 (8 in flight); k scattered to transposed
// [w*7+j][c] rows with increment index math. Dots: 32 x LDS.128 + 64 FMA.
// ---------------------------------------------------------------------------
__global__ __launch_bounds__(384) void ax_attn_logits(
    const float* __restrict__ qH, const float* __restrict__ kH,
    const float* __restrict__ qW, const float* __restrict__ kW)
{
    extern __shared__ float smA[];
    float* sQH = smA;              // 49 rows * 68
    float* sKH = smA + 3332;       // transposed: 49 rows * 68  ([w*7+j][c])
    float* sQW = smA + 6664;       // 49 * 68
    float* sKW = smA + 9996;       // 49 * 68
    float* sL  = smA + 13328;      // 49 * 16

    const int n   = blockIdx.x;
    const int tid = threadIdx.x;

    const float4* q1 = (const float4*)(qH + (size_t)n * 3136);
    const float4* q2 = (const float4*)(qW + (size_t)n * 3136);
    const float4* k1 = (const float4*)(kH + (size_t)n * 3136);
    const float4* k2 = (const float4*)(kW + (size_t)n * 3136);

    // helper lambda-free k scatter: element base r=4*r4 inside w-row
    // burst staging: 2 uniform rounds (i4 = tid, tid+384), then tail (tid<16)
    {
        float4 a0q, a1q, b0q, b1q, a0k, a1k, b0k, b1k;
        int ia = tid, ib = tid + 384;
        a0q = q1[ia]; b0q = q2[ia]; a0k = k1[ia]; b0k = k2[ia];
        if (ib < 784) { a1q = q1[ib]; b1q = q2[ib]; a1k = k1[ib]; b1k = k2[ib]; }

        // store round a
        {
            int g = ia >> 4, c4 = ia & 15;
            ((float4*)(sQH + g * 68))[c4] = a0q;
            ((float4*)(sQW + g * 68))[c4] = b0q;
            int w = ia / 112, r4 = ia - w * 112, r = 4 * r4;
            int c = r / 7, j = r - 7 * c;
            float av[4] = {a0k.x, a0k.y, a0k.z, a0k.w};
            float bv[4] = {b0k.x, b0k.y, b0k.z, b0k.w};
            #pragma unroll
            for (int e = 0; e < 4; e++) {
                sKH[(w * 7 + j) * 68 + c] = av[e];
                sKW[(w * 7 + j) * 68 + c] = bv[e];
                if (++j == 7) { j = 0; c++; }
            }
        }
        // store round b
        if (ib < 784) {
            int g = ib >> 4, c4 = ib & 15;
            ((float4*)(sQH + g * 68))[c4] = a1q;
            ((float4*)(sQW + g * 68))[c4] = b1q;
            int w = ib / 112, r4 = ib - w * 112, r = 4 * r4;
            int c = r / 7, j = r - 7 * c;
            float av[4] = {a1k.x, a1k.y, a1k.z, a1k.w};
            float bv[4] = {b1k.x, b1k.y, b1k.z, b1k.w};
            #pragma unroll
            for (int e = 0; e < 4; e++) {
                sKH[(w * 7 + j) * 68 + c] = av[e];
                sKW[(w * 7 + j) * 68 + c] = bv[e];
                if (++j == 7) { j = 0; c++; }
            }
        }
        // tail: i4 = 768..783 (tid < 16)
        if (tid < 16) {
            int ic = tid + 768;
            float4 aq = q1[ic], bq = q2[ic], ak = k1[ic], bk = k2[ic];
            int g = ic >> 4, c4 = ic & 15;
            ((float4*)(sQH + g * 68))[c4] = aq;
            ((float4*)(sQW + g * 68))[c4] = bq;
            int w = ic / 112, r4 = ic - w * 112, r = 4 * r4;
            int c = r / 7, j = r - 7 * c;
            float av[4] = {ak.x, ak.y, ak.z, ak.w};
            float bv[4] = {bk.x, bk.y, bk.z, bk.w};
            #pragma unroll
            for (int e = 0; e < 4; e++) {
                sKH[(w * 7 + j) * 68 + c] = av[e];
                sKW[(w * 7 + j) * 68 + c] = bv[e];
                if (++j == 7) { j = 0; c++; }
            }
        }
    }
    __syncthreads();

    if (tid < 343) {
        const int a0 = tid / 49;
        const int r  = tid - a0 * 49;
        const int a1 = r / 7;
        const int a2 = r - a1 * 7;

        // H: logits[n, h=a1, w=a0, a2] = dot(qH[n,a0,a1,:], kH[n,a0,:,a2])
        {
            const float4* q = (const float4*)(sQH + (a0 * 7 + a1) * 68);
            const float4* k = (const float4*)(sKH + (a0 * 7 + a2) * 68);
            float s = 0.f;
            #pragma unroll
            for (int c4 = 0; c4 < 16; c4++) {
                float4 qa = q[c4], ka = k[c4];
                s = fmaf(qa.x, ka.x, s); s = fmaf(qa.y, ka.y, s);
                s = fmaf(qa.z, ka.z, s); s = fmaf(qa.w, ka.w, s);
            }
            sL[(a1 * 7 + a0) * 16 + a2] = (a1 == a2) ? NEGV : s;
        }
        // W: logits[n, h=a0, w=a1, 8+a2] = dot(qW[n,a0,a1,:], kW[n,a0,:,a2])
        {
            const float4* q = (const float4*)(sQW + (a0 * 7 + a1) * 68);
            const float4* k = (const float4*)(sKW + (a0 * 7 + a2) * 68);
            float s = 0.f;
            #pragma unroll
            for (int c4 = 0; c4 < 16; c4++) {
                float4 qa = q[c4], ka = k[c4];
                s = fmaf(qa.x, ka.x, s); s = fmaf(qa.y, ka.y, s);
                s = fmaf(qa.z, ka.z, s); s = fmaf(qa.w, ka.w, s);
            }
            sL[(a0 * 7 + a1) * 16 + 8 + a2] = s;
        }
    }
    __syncthreads();

    if (tid < GG) {
        const float* row = sL + tid * 16;
        float m = row[0];
        #pragma unroll
        for (int i = 1; i < 7; i++)  m = fmaxf(m, row[i]);
        #pragma unroll
        for (int i = 8; i < 15; i++) m = fmaxf(m, row[i]);
        float e[16], sum = 0.f;
        #pragma unroll
        for (int i = 0; i < 7; i++)  { e[i] = __expf(row[i] - m); sum += e[i]; }
        #pragma unroll
        for (int i = 8; i < 15; i++) { e[i] = __expf(row[i] - m); sum += e[i]; }
        e[7] = 0.f; e[15] = 0.f;
        float inv = 1.f / sum;
        float4* dst = (float4*)&g_p[((size_t)n * GG + tid) * 16];
        dst[0] = make_float4(e[0] * inv,  e[1] * inv,  e[2] * inv,  e[3] * inv);
        dst[1] = make_float4(e[4] * inv,  e[5] * inv,  e[6] * inv,  0.f);
        dst[2] = make_float4(e[8] * inv,  e[9] * inv,  e[10] * inv, e[11] * inv);
        dst[3] = make_float4(e[12] * inv, e[13] * inv, e[14] * inv, 0.f);
    }
}

// ---------------------------------------------------------------------------
// Kernel B: out[n,c,h,w] = sum_j p[pos][j]*vH[n,w,c,j] + sum_y p[pos][8+y]*vW[n,h,c,y]
// grid = (N, Cv/128), block = 128 (lane = channel in 128-chunk).
// Staging in 3 bursts of 8 independent LDG.128 (high MLP); natural V layout,
// lane-stride-7 conflict-free compute reads; vh cached in 49 regs; output
// staged in aliased sVH for coalesced float4 STG.
// ---------------------------------------------------------------------------
__global__ __launch_bounds__(128, 4) void ax_attn_out(
    const float* __restrict__ vH, const float* __restrict__ vW,
    float* __restrict__ out, int Cv)
{
    extern __shared__ float smB[];
    float* sVH = smB;            // [g][c][j] 7*128*7 = 6272 (aliased as sOut)
    float* sVW = smB + 6272;
    float* sP  = smB + 12544;    // 49*16

    const int n   = blockIdx.x;
    const int c0  = blockIdx.y * 128;
    const int tid = threadIdx.x;
    const int rs4 = Cv * 7 / 4;  // global row stride per g, in float4

    const float4* gH = (const float4*)(vH + ((size_t)n * 7 * Cv + c0) * 7);
    const float4* gW = (const float4*)(vW + ((size_t)n * 7 * Cv + c0) * 7);
    const float4* pg = (const float4*)&g_p[(size_t)n * GG * 16];

    // p loads first (independent)
    float4 p0 = pg[tid];
    float4 p1; bool hp1 = (tid < 68);
    if (hp1) p1 = pg[tid + 128];

    // 3 bursts x 4 iters: 1536 float4 per array; tail 32 by first warp
    #pragma unroll
    for (int u = 0; u < 3; u++) {
        float4 bh[4], bw[4];
        #pragma unroll
        for (int k2 = 0; k2 < 4; k2++) {
            int i = tid + u * 512 + k2 * 128;
            int g = i / 224, r = i - g * 224;
            size_t s = (size_t)g * rs4 + r;
            bh[k2] = gH[s]; bw[k2] = gW[s];
        }
        #pragma unroll
        for (int k2 = 0; k2 < 4; k2++) {
            int i = tid + u * 512 + k2 * 128;
            ((float4*)sVH)[i] = bh[k2];
            ((float4*)sVW)[i] = bw[k2];
        }
    }
    if (tid < 32) {   // i = 1536..1567 -> g = 6, r = i - 1344
        int i = 1536 + tid, r = i - 1344;
        size_t s = (size_t)6 * rs4 + r;
        ((float4*)sVH)[i] = gH[s];
        ((float4*)sVW)[i] = gW[s];
    }
    ((float4*)sP)[tid] = p0;
    if (hp1) ((float4*)sP)[tid + 128] = p1;
    __syncthreads();

    // cache this thread's vH (lane stride 7 -> conflict-free)
    float vh[49];
    #pragma unroll
    for (int w = 0; w < 7; w++)
        #pragma unroll
        for (int j = 0; j < 7; j++)
            vh[w * 7 + j] = sVH[w * 896 + tid * 7 + j];
    __syncthreads();   // all vH consumed -> safe to alias as sOut

    float* sOut = sVH;
    #pragma unroll
    for (int h = 0; h < 7; h++) {
        float vw0 = sVW[h * 896 + tid * 7 + 0];
        float vw1 = sVW[h * 896 + tid * 7 + 1];
        float vw2 = sVW[h * 896 + tid * 7 + 2];
        float vw3 = sVW[h * 896 + tid * 7 + 3];
        float vw4 = sVW[h * 896 + tid * 7 + 4];
        float vw5 = sVW[h * 896 + tid * 7 + 5];
        float vw6 = sVW[h * 896 + tid * 7 + 6];
        #pragma unroll
        for (int w = 0; w < 7; w++) {
            const float4* p4 = (const float4*)(sP + (h * 7 + w) * 16);
            float4 a = p4[0], b = p4[1], c4 = p4[2], d4 = p4[3];
            float s = a.x * vh[w * 7 + 0];
            s = fmaf(a.y, vh[w * 7 + 1], s);
            s = fmaf(a.z, vh[w * 7 + 2], s);
            s = fmaf(a.w, vh[w * 7 + 3], s);
            s = fmaf(b.x, vh[w * 7 + 4], s);
            s = fmaf(b.y, vh[w * 7 + 5], s);
            s = fmaf(b.z, vh[w * 7 + 6], s);
            s = fmaf(c4.x, vw0, s);
            s = fmaf(c4.y, vw1, s);
            s = fmaf(c4.z, vw2, s);
            s = fmaf(c4.w, vw3, s);
            s = fmaf(d4.x, vw4, s);
            s = fmaf(d4.y, vw5, s);
            s = fmaf(d4.z, vw6, s);
            sOut[tid * 49 + h * 7 + w] = s;   // stride 49 (coprime 32)
        }
    }
    __syncthreads();

    // coalesced float4 write-out
    float* dst = out + ((size_t)n * Cv + c0) * GG;
    #pragma unroll
    for (int u = 0; u < 12; u++)
        ((float4*)dst)[tid + u * 128] = ((const float4*)sOut)[tid + u * 128];
    if (tid < 32)
        ((float4*)dst)[1536 + tid] = ((const float4*)sOut)[1536 + tid];
}

// ---------------------------------------------------------------------------
extern "C" void kernel_launch(void* const* d_in, const int* in_sizes, int n_in,
                              void* d_out, int out_size)
{
    const float* qH = (const float*)d_in[0];
    const float* kH = (const float*)d_in[1];
    const float* vH = (const float*)d_in[2];
    const float* kW = (const float*)d_in[4];
    const float* qW = (const float*)d_in[3];
    const float* vW = (const float*)d_in[5];

    const int B  = in_sizes[0] / (7 * CQ);    // 3584
    const int N  = B / 7;                     // 512
    const int Cv = in_sizes[2] / (B * 7);     // 512

    const size_t smemA = (size_t)14112 * sizeof(float);  // 56448
    const size_t smemB = (size_t)13328 * sizeof(float);  // 53312
    cudaFuncSetAttribute(ax_attn_logits, cudaFuncAttributeMaxDynamicSharedMemorySize, (int)smemA);
    cudaFuncSetAttribute(ax_attn_out,    cudaFuncAttributeMaxDynamicSharedMemorySize, (int)smemB);

    ax_attn_logits<<<N, 384, smemA>>>(qH, kH, qW, kW);
    ax_attn_out<<<dim3(N, Cv / 128), 128, smemB>>>(vH, vW, (float*)d_out, Cv);
}

// round 8
// speedup vs baseline: 2.2244x; 1.1867x over previous
#include <cuda_runtime.h>

#define GG    49
#define CQ    64
#define NEGV  (-1e20f)

// Softmax probabilities scratch: [n][49][16]; pH at slots 0..6 (7=0), pW at 8..14 (15=0).
__device__ float g_p[512 * GG * 16];

// ---------------------------------------------------------------------------
// Kernel A: logits (H diag-masked + W) + softmax over 14, per n.
// grid = N, block = 384, dyn smem 56448 B -> 4 blocks/SM (48 warps).
// Staging: burst-batched LDG.128 (8 in flight); k scattered to transposed
// [w*7+j][c] rows with increment index math. Dots: 32 x LDS.128 + 64 FMA.
// ---------------------------------------------------------------------------
__global__ __launch_bounds__(384) void ax_attn_logits(
    const float* __restrict__ qH, const float* __restrict__ kH,
    const float* __restrict__ qW, const float* __restrict__ kW)
{
    extern __shared__ float smA[];
    float* sQH = smA;              // 49 rows * 68
    float* sKH = smA + 3332;       // transposed: 49 rows * 68  ([w*7+j][c])
    float* sQW = smA + 6664;       // 49 * 68
    float* sKW = smA + 9996;       // 49 * 68
    float* sL  = smA + 13328;      // 49 * 16

    const int n   = blockIdx.x;
    const int tid = threadIdx.x;

    const float4* q1 = (const float4*)(qH + (size_t)n * 3136);
    const float4* q2 = (const float4*)(qW + (size_t)n * 3136);
    const float4* k1 = (const float4*)(kH + (size_t)n * 3136);
    const float4* k2 = (const float4*)(kW + (size_t)n * 3136);

    // burst staging: 2 uniform rounds (i4 = tid, tid+384), then tail (tid<16)
    {
        float4 a0q, a1q, b0q, b1q, a0k, a1k, b0k, b1k;
        int ia = tid, ib = tid + 384;
        a0q = q1[ia]; b0q = q2[ia]; a0k = k1[ia]; b0k = k2[ia];
        if (ib < 784) { a1q = q1[ib]; b1q = q2[ib]; a1k = k1[ib]; b1k = k2[ib]; }

        {
            int g = ia >> 4, c4 = ia & 15;
            ((float4*)(sQH + g * 68))[c4] = a0q;
            ((float4*)(sQW + g * 68))[c4] = b0q;
            int w = ia / 112, r4 = ia - w * 112, r = 4 * r4;
            int c = r / 7, j = r - 7 * c;
            float av[4] = {a0k.x, a0k.y, a0k.z, a0k.w};
            float bv[4] = {b0k.x, b0k.y, b0k.z, b0k.w};
            #pragma unroll
            for (int e = 0; e < 4; e++) {
                sKH[(w * 7 + j) * 68 + c] = av[e];
                sKW[(w * 7 + j) * 68 + c] = bv[e];
                if (++j == 7) { j = 0; c++; }
            }
        }
        if (ib < 784) {
            int g = ib >> 4, c4 = ib & 15;
            ((float4*)(sQH + g * 68))[c4] = a1q;
            ((float4*)(sQW + g * 68))[c4] = b1q;
            int w = ib / 112, r4 = ib - w * 112, r = 4 * r4;
            int c = r / 7, j = r - 7 * c;
            float av[4] = {a1k.x, a1k.y, a1k.z, a1k.w};
            float bv[4] = {b1k.x, b1k.y, b1k.z, b1k.w};
            #pragma unroll
            for (int e = 0; e < 4; e++) {
                sKH[(w * 7 + j) * 68 + c] = av[e];
                sKW[(w * 7 + j) * 68 + c] = bv[e];
                if (++j == 7) { j = 0; c++; }
            }
        }
        if (tid < 16) {
            int ic = tid + 768;
            float4 aq = q1[ic], bq = q2[ic], ak = k1[ic], bk = k2[ic];
            int g = ic >> 4, c4 = ic & 15;
            ((float4*)(sQH + g * 68))[c4] = aq;
            ((float4*)(sQW + g * 68))[c4] = bq;
            int w = ic / 112, r4 = ic - w * 112, r = 4 * r4;
            int c = r / 7, j = r - 7 * c;
            float av[4] = {ak.x, ak.y, ak.z, ak.w};
            float bv[4] = {bk.x, bk.y, bk.z, bk.w};
            #pragma unroll
            for (int e = 0; e < 4; e++) {
                sKH[(w * 7 + j) * 68 + c] = av[e];
                sKW[(w * 7 + j) * 68 + c] = bv[e];
                if (++j == 7) { j = 0; c++; }
            }
        }
    }
    __syncthreads();

    if (tid < 343) {
        const int a0 = tid / 49;
        const int r  = tid - a0 * 49;
        const int a1 = r / 7;
        const int a2 = r - a1 * 7;

        // H: logits[n, h=a1, w=a0, a2] = dot(qH[n,a0,a1,:], kH[n,a0,:,a2])
        {
            const float4* q = (const float4*)(sQH + (a0 * 7 + a1) * 68);
            const float4* k = (const float4*)(sKH + (a0 * 7 + a2) * 68);
            float s = 0.f;
            #pragma unroll
            for (int c4 = 0; c4 < 16; c4++) {
                float4 qa = q[c4], ka = k[c4];
                s = fmaf(qa.x, ka.x, s); s = fmaf(qa.y, ka.y, s);
                s = fmaf(qa.z, ka.z, s); s = fmaf(qa.w, ka.w, s);
            }
            sL[(a1 * 7 + a0) * 16 + a2] = (a1 == a2) ? NEGV : s;
        }
        // W: logits[n, h=a0, w=a1, 8+a2] = dot(qW[n,a0,a1,:], kW[n,a0,:,a2])
        {
            const float4* q = (const float4*)(sQW + (a0 * 7 + a1) * 68);
            const float4* k = (const float4*)(sKW + (a0 * 7 + a2) * 68);
            float s = 0.f;
            #pragma unroll
            for (int c4 = 0; c4 < 16; c4++) {
                float4 qa = q[c4], ka = k[c4];
                s = fmaf(qa.x, ka.x, s); s = fmaf(qa.y, ka.y, s);
                s = fmaf(qa.z, ka.z, s); s = fmaf(qa.w, ka.w, s);
            }
            sL[(a0 * 7 + a1) * 16 + 8 + a2] = s;
        }
    }
    __syncthreads();

    if (tid < GG) {
        const float* row = sL + tid * 16;
        float m = row[0];
        #pragma unroll
        for (int i = 1; i < 7; i++)  m = fmaxf(m, row[i]);
        #pragma unroll
        for (int i = 8; i < 15; i++) m = fmaxf(m, row[i]);
        float e[16], sum = 0.f;
        #pragma unroll
        for (int i = 0; i < 7; i++)  { e[i] = __expf(row[i] - m); sum += e[i]; }
        #pragma unroll
        for (int i = 8; i < 15; i++) { e[i] = __expf(row[i] - m); sum += e[i]; }
        e[7] = 0.f; e[15] = 0.f;
        float inv = 1.f / sum;
        float4* dst = (float4*)&g_p[((size_t)n * GG + tid) * 16];
        dst[0] = make_float4(e[0] * inv,  e[1] * inv,  e[2] * inv,  0.f);
        dst[0] = make_float4(e[0] * inv,  e[1] * inv,  e[2] * inv,  e[3] * inv);
        dst[1] = make_float4(e[4] * inv,  e[5] * inv,  e[6] * inv,  0.f);
        dst[2] = make_float4(e[8] * inv,  e[9] * inv,  e[10] * inv, e[11] * inv);
        dst[3] = make_float4(e[12] * inv, e[13] * inv, e[14] * inv, 0.f);
    }
}

// ---------------------------------------------------------------------------
// Kernel B: out[n,c,h,w] = sum_j p[pos][j]*vH[n,w,c,j] + sum_y p[pos][8+y]*vW[n,h,c,y]
// grid = (N, Cv/128), block = 128 (lane = channel in 128-chunk).
// V loaded DIRECTLY GMEM->registers (each element has exactly one consumer):
// 49 vh LDGs issued as one batch (huge MLP), vw streamed per h. No V smem,
// no V sync. smem = sOut + sP = 28.2KB -> 5 blocks/SM (20 warps), 102-reg cap.
// ---------------------------------------------------------------------------
__global__ __launch_bounds__(128, 5) void ax_attn_out(
    const float* __restrict__ vH, const float* __restrict__ vW,
    float* __restrict__ out, int Cv)
{
    __shared__ float sOut[7 * 7 * 128];   // [c][pos] transposed staging, 6272
    __shared__ float sP[GG * 16];         // 784

    const int n   = blockIdx.x;
    const int c0  = blockIdx.y * 128;
    const int tid = threadIdx.x;
    const int c   = c0 + tid;
    const int ws  = Cv * 7;               // per-g stride in floats

    const float* bH = vH + (size_t)n * Cv * 49 + (size_t)c * 7;
    const float* bW = vW + (size_t)n * Cv * 49 + (size_t)c * 7;

    // ---- direct GMEM->reg vH loads: 49 independent LDGs, issued up front ----
    float vh[49];
    #pragma unroll
    for (int w = 0; w < 7; w++)
        #pragma unroll
        for (int j = 0; j < 7; j++)
            vh[w * 7 + j] = bH[w * ws + j];

    // ---- stage p to smem (overlaps with vh loads in flight) ----
    {
        const float4* pg = (const float4*)&g_p[(size_t)n * GG * 16];
        float4 p0 = pg[tid];
        float4 p1; bool hp1 = (tid < 68);
        if (hp1) p1 = pg[tid + 128];
        ((float4*)sP)[tid] = p0;
        if (hp1) ((float4*)sP)[tid + 128] = p1;
    }
    __syncthreads();

    #pragma unroll
    for (int h = 0; h < 7; h++) {
        const float* bWh = bW + h * ws;
        float vw0 = bWh[0], vw1 = bWh[1], vw2 = bWh[2], vw3 = bWh[3];
        float vw4 = bWh[4], vw5 = bWh[5], vw6 = bWh[6];
        #pragma unroll
        for (int w = 0; w < 7; w++) {
            const float4* p4 = (const float4*)(sP + (h * 7 + w) * 16);
            float4 a = p4[0], b = p4[1], c4 = p4[2], d4 = p4[3];
            float s = a.x * vh[w * 7 + 0];
            s = fmaf(a.y, vh[w * 7 + 1], s);
            s = fmaf(a.z, vh[w * 7 + 2], s);
            s = fmaf(a.w, vh[w * 7 + 3], s);
            s = fmaf(b.x, vh[w * 7 + 4], s);
            s = fmaf(b.y, vh[w * 7 + 5], s);
            s = fmaf(b.z, vh[w * 7 + 6], s);
            s = fmaf(c4.x, vw0, s);
            s = fmaf(c4.y, vw1, s);
            s = fmaf(c4.z, vw2, s);
            s = fmaf(c4.w, vw3, s);
            s = fmaf(d4.x, vw4, s);
            s = fmaf(d4.y, vw5, s);
            s = fmaf(d4.z, vw6, s);
            sOut[tid * 49 + h * 7 + w] = s;   // stride 49 (coprime 32) -> conflict-free
        }
    }
    __syncthreads();

    // coalesced float4 write-out: sOut[c_local*49 + pos] == out[n, c0+c_local, pos]
    float* dst = out + ((size_t)n * Cv + c0) * GG;
    #pragma unroll
    for (int u = 0; u < 12; u++)
        ((float4*)dst)[tid + u * 128] = ((const float4*)sOut)[tid + u * 128];
    if (tid < 32)
        ((float4*)dst)[1536 + tid] = ((const float4*)sOut)[1536 + tid];
}

// ---------------------------------------------------------------------------
extern "C" void kernel_launch(void* const* d_in, const int* in_sizes, int n_in,
                              void* d_out, int out_size)
{
    const float* qH = (const float*)d_in[0];
    const float* kH = (const float*)d_in[1];
    const float* vH = (const float*)d_in[2];
    const float* qW = (const float*)d_in[3];
    const float* kW = (const float*)d_in[4];
    const float* vW = (const float*)d_in[5];

    const int B  = in_sizes[0] / (7 * CQ);    // 3584
    const int N  = B / 7;                     // 512
    const int Cv = in_sizes[2] / (B * 7);     // 512

    const size_t smemA = (size_t)14112 * sizeof(float);  // 56448
    cudaFuncSetAttribute(ax_attn_logits, cudaFuncAttributeMaxDynamicSharedMemorySize, (int)smemA);

    ax_attn_logits<<<N, 384, smemA>>>(qH, kH, qW, kW);
    ax_attn_out<<<dim3(N, Cv / 128), 128>>>(vH, vW, (float*)d_out, Cv);
}